// round 15
// baseline (speedup 1.0000x reference)
#include <cuda_runtime.h>
#include <cstdint>

#define NCHAN 128
#define LSIG 131072
#define K 4
#define NSUB 8                  /* sub-blocks (CTAs) per channel */
#define CTA_T 128               /* threads per hot CTA */
#define CHUNK 64                /* samples per chunk */
#define SUBLEN 16384            /* samples per sub-block = 256 chunks * 64 */
#define NPAIR 1024              /* chunk pairs per channel */
#define TILE 32                 /* samples per chunk per staged tile */
#define NTILES (CHUNK/TILE)     /* 2 */
#define ROW 68                  /* floats per interleaved row: 16B-mult, 17 odd 16B-units */
#define SMEM_FLOATS (CTA_T*ROW) /* 8704 floats = 34816 B */
#define LEVELS 10               /* scan levels over 1024 pair-aggregates */

typedef unsigned long long u64;

__device__ float g_W[NCHAN][NPAIR][2][8];   // zero-init end states (lo,hi) per pair
__device__ float g_I[NCHAN][NPAIR][2][8];   // true initial states (lo,hi) per pair

__device__ __forceinline__ u64 pk2(float lo, float hi) {
    u64 r; asm("mov.b64 %0,{%1,%2};" : "=l"(r) : "f"(lo), "f"(hi)); return r;
}
__device__ __forceinline__ void upk2(u64 v, float& lo, float& hi) {
    asm("mov.b64 {%0,%1},%2;" : "=f"(lo), "=f"(hi) : "l"(v));
}
__device__ __forceinline__ u64 fma2(u64 a, u64 b, u64 c) {
    u64 d; asm("fma.rn.f32x2 %0,%1,%2,%3;" : "=l"(d) : "l"(a), "l"(b), "l"(c)); return d;
}
__device__ __forceinline__ u64 mul2(u64 a, u64 b) {
    u64 d; asm("mul.rn.f32x2 %0,%1,%2;" : "=l"(d) : "l"(a), "l"(b)); return d;
}

struct Coef { float b0[K], b1[K], b2[K], na1[K], na2[K]; };
struct Coef2 { u64 b0[K], b1[K], b2[K], na1[K], na2[K]; };

__device__ __forceinline__ void load_coef(const float* __restrict__ Bs,
                                          const float* __restrict__ As,
                                          int ch, Coef& cf)
{
    const float* bs = Bs + (size_t)ch * K * 3;
    const float* as = As + (size_t)ch * K * 3;
#pragma unroll
    for (int k = 0; k < K; ++k) {
        float inv = 1.0f / as[k * 3 + 0];
        cf.b0[k]  = bs[k * 3 + 0] * inv;
        cf.b1[k]  = bs[k * 3 + 1] * inv;
        cf.b2[k]  = bs[k * 3 + 2] * inv;
        cf.na1[k] = -(as[k * 3 + 1] * inv);
        cf.na2[k] = -(as[k * 3 + 2] * inv);
    }
}

__device__ __forceinline__ void pack_coef(const Coef& cf, Coef2& c2)
{
#pragma unroll
    for (int k = 0; k < K; ++k) {
        c2.b0[k]  = pk2(cf.b0[k],  cf.b0[k]);
        c2.b1[k]  = pk2(cf.b1[k],  cf.b1[k]);
        c2.b2[k]  = pk2(cf.b2[k],  cf.b2[k]);
        c2.na1[k] = pk2(cf.na1[k], cf.na1[k]);
        c2.na2[k] = pk2(cf.na2[k], cf.na2[k]);
    }
}

__device__ __forceinline__ float cascade_step(float u, float s1[K], float s2[K], const Coef& cf) {
#pragma unroll
    for (int k = 0; k < K; ++k) {
        float y = fmaf(cf.b0[k], u, s1[k]);
        s1[k] = fmaf(cf.b1[k], u, fmaf(cf.na1[k], y, s2[k]));
        s2[k] = fmaf(cf.b2[k], u, cf.na2[k] * y);
        u = y;
    }
    return u;
}

__device__ __forceinline__ u64 cascade_step2(u64 u, u64 s1[K], u64 s2[K], const Coef2& cf) {
#pragma unroll
    for (int k = 0; k < K; ++k) {
        u64 y = fma2(cf.b0[k], u, s1[k]);
        s1[k] = fma2(cf.b1[k], u, fma2(cf.na1[k], y, s2[k]));
        s2[k] = fma2(cf.b2[k], u, mul2(cf.na2[k], y));
        u = y;
    }
    return u;
}

// stage one tile: interleave lo/hi quads in registers, wide STS.128 only
__device__ __forceinline__ void stage_tile(const float* __restrict__ xs, float* __restrict__ sm,
                                           int tile, int tid)
{
#pragma unroll
    for (int it = 0; it < 8; ++it) {
        int f = tid + it * CTA_T;            // 0..1023
        int r = f >> 3, w = f & 7;           // row 0..127, quad 0..7
        const float* src = xs + (size_t)r * (2 * CHUNK) + tile * TILE + w * 4;
        float4 lo = *reinterpret_cast<const float4*>(src);
        float4 hi = *reinterpret_cast<const float4*>(src + CHUNK);
        float* p = sm + r * ROW + (w << 3);
        *reinterpret_cast<float4*>(p)     = make_float4(lo.x, hi.x, lo.y, hi.y);
        *reinterpret_cast<float4*>(p + 4) = make_float4(lo.z, hi.z, lo.w, hi.w);
    }
}

// ============================ Kernel A: zero-init pass ========================
extern __shared__ float smA[];

__global__ void __launch_bounds__(CTA_T, 6)
pass_a_kernel(const float* __restrict__ x,
              const float* __restrict__ Bs,
              const float* __restrict__ As)
{
    const int cta = blockIdx.x;          // 0..1023
    const int ch  = cta >> 3;
    const int q   = cta & 7;
    const int tid = threadIdx.x;

    Coef cf;  load_coef(Bs, As, ch, cf);
    Coef2 c2; pack_coef(cf, c2);

    const float* __restrict__ xs = x + (size_t)ch * LSIG + (size_t)q * SUBLEN;

    u64 s1[K] = {0,0,0,0}, s2[K] = {0,0,0,0};
    const float4* __restrict__ rrow = reinterpret_cast<const float4*>(smA + tid * ROW);

#pragma unroll 1
    for (int tile = 0; tile < NTILES; ++tile) {
        if (tile) __syncthreads();       // previous tile reads done
        stage_tile(xs, smA, tile, tid);
        __syncthreads();
#pragma unroll
        for (int j2 = 0; j2 < TILE / 2; ++j2) {
            float4 v = rrow[j2];
            cascade_step2(pk2(v.x, v.y), s1, s2, c2);
            cascade_step2(pk2(v.z, v.w), s1, s2, c2);
        }
    }

    const int p = q * CTA_T + tid;       // global pair index in channel
    float* w0 = g_W[ch][p][0];
    float* w1 = g_W[ch][p][1];
#pragma unroll
    for (int k = 0; k < K; ++k) {
        float lo, hi;
        upk2(s1[k], lo, hi); w0[2*k]   = lo; w1[2*k]   = hi;
        upk2(s2[k], lo, hi); w0[2*k+1] = lo; w1[2*k+1] = hi;
    }
}

// ============================ Kernel B: scan ==================================
__global__ void __launch_bounds__(1024, 1)
scan_kernel(const float* __restrict__ Bs, const float* __restrict__ As)
{
    __shared__ float S[1024][8];
    __shared__ float Mats[LEVELS][8][8];   // A^(128 * 2^l), l=0..9
    __shared__ float A64[8][8];
    __shared__ float P[8][8];

    const int ch  = blockIdx.x;
    const int tid = threadIdx.x;

    Coef cf; load_coef(Bs, As, ch, cf);

    if (tid < 8) {
        float t1[K], t2[K];
#pragma unroll
        for (int k = 0; k < K; ++k) {
            t1[k] = (2 * k     == tid) ? 1.f : 0.f;
            t2[k] = (2 * k + 1 == tid) ? 1.f : 0.f;
        }
        cascade_step(0.f, t1, t2, cf);
#pragma unroll
        for (int k = 0; k < K; ++k) {
            P[2 * k][tid]     = t1[k];
            P[2 * k + 1][tid] = t2[k];
        }
    }

    // load this pair's zero-init states (overlaps squaring below)
    float w0[8], w1[8];
#pragma unroll
    for (int i = 0; i < 8; ++i) { w0[i] = g_W[ch][tid][0][i]; w1[i] = g_W[ch][tid][1][i]; }

    // squaring by warps 0-1: A64 = A^(2^6); Mats[it-7] = A^(2^it), it=7..16
    if (tid < 64) {
        const int r = tid >> 3, c = tid & 7;
        asm volatile("bar.sync 1, 64;" ::: "memory");
        for (int it = 1; it <= 16; ++it) {
            float val = 0.f;
#pragma unroll
            for (int kk = 0; kk < 8; ++kk) val = fmaf(P[r][kk], P[kk][c], val);
            asm volatile("bar.sync 1, 64;" ::: "memory");
            P[r][c] = val;
            if (it == 6) A64[r][c] = val;
            if (it >= 7) Mats[it - 7][r][c] = val;
            asm volatile("bar.sync 1, 64;" ::: "memory");
        }
    }
    __syncthreads();

    // pair combine: agg = A64*w0 + w1
    float agg[8];
#pragma unroll
    for (int r = 0; r < 8; ++r) {
        float acc = w1[r];
#pragma unroll
        for (int c = 0; c < 8; ++c) acc = fmaf(A64[r][c], w0[c], acc);
        agg[r] = acc;
        S[tid][r] = acc;
    }
    __syncthreads();

    // Kogge-Stone over 1024 aggregates
    for (int l = 0; l < LEVELS; ++l) {
        int d = 1 << l;
        float t[8];
        bool act = (tid >= d);
        if (act) {
#pragma unroll
            for (int i = 0; i < 8; ++i) t[i] = S[tid - d][i];
        }
        __syncthreads();
        if (act) {
#pragma unroll
            for (int r = 0; r < 8; ++r) {
                float acc = agg[r];
#pragma unroll
                for (int c = 0; c < 8; ++c) acc = fmaf(Mats[l][r][c], t[c], acc);
                agg[r] = acc;
            }
#pragma unroll
            for (int i = 0; i < 8; ++i) S[tid][i] = agg[i];
        }
        __syncthreads();
    }

    // exclusive -> init0; init1 = A64*init0 + w0
    float init0[8], init1[8];
    if (tid == 0) {
#pragma unroll
        for (int i = 0; i < 8; ++i) init0[i] = 0.f;
    } else {
#pragma unroll
        for (int i = 0; i < 8; ++i) init0[i] = S[tid - 1][i];
    }
#pragma unroll
    for (int r = 0; r < 8; ++r) {
        float acc = w0[r];
#pragma unroll
        for (int c = 0; c < 8; ++c) acc = fmaf(A64[r][c], init0[c], acc);
        init1[r] = acc;
    }

#pragma unroll
    for (int i = 0; i < 8; ++i) {
        g_I[ch][tid][0][i] = init0[i];
        g_I[ch][tid][1][i] = init1[i];
    }
}

// ============================ Kernel C: output pass ===========================
extern __shared__ float smC[];

__global__ void __launch_bounds__(CTA_T, 6)
pass_c_kernel(const float* __restrict__ x,
              const float* __restrict__ Bs,
              const float* __restrict__ As,
              float* __restrict__ yout)
{
    const int cta = blockIdx.x;
    const int ch  = cta >> 3;
    const int q   = cta & 7;
    const int tid = threadIdx.x;

    Coef cf;  load_coef(Bs, As, ch, cf);
    Coef2 c2; pack_coef(cf, c2);

    const float* __restrict__ xs = x + (size_t)ch * LSIG + (size_t)q * SUBLEN;
    float* __restrict__ ys = yout + (size_t)ch * LSIG + (size_t)q * SUBLEN;

    const int p = q * CTA_T + tid;
    u64 s1[K], s2[K];
    {
        const float* i0 = g_I[ch][p][0];
        const float* i1 = g_I[ch][p][1];
#pragma unroll
        for (int k = 0; k < K; ++k) {
            s1[k] = pk2(i0[2*k],   i1[2*k]);
            s2[k] = pk2(i0[2*k+1], i1[2*k+1]);
        }
    }

    float4* __restrict__ wrow = reinterpret_cast<float4*>(smC + tid * ROW);

#pragma unroll 1
    for (int tile = 0; tile < NTILES; ++tile) {
        if (tile) __syncthreads();       // previous tile drain reads done
        stage_tile(xs, smC, tile, tid);
        __syncthreads();
#pragma unroll
        for (int j2 = 0; j2 < TILE / 2; ++j2) {
            float4 v = wrow[j2];
            u64 y0 = cascade_step2(pk2(v.x, v.y), s1, s2, c2);
            u64 y1 = cascade_step2(pk2(v.z, v.w), s1, s2, c2);
            float4 o;
            upk2(y0, o.x, o.y);
            upk2(y1, o.z, o.w);
            wrow[j2] = o;
        }
        __syncthreads();
        // drain: de-interleave in registers, wide stores
#pragma unroll
        for (int it = 0; it < 8; ++it) {
            int f = tid + it * CTA_T;
            int r = f >> 3, w = f & 7;
            const float* pp = smC + r * ROW + (w << 3);
            float4 a = *reinterpret_cast<const float4*>(pp);
            float4 b = *reinterpret_cast<const float4*>(pp + 4);
            float* dst = ys + (size_t)r * (2 * CHUNK) + tile * TILE + w * 4;
            *reinterpret_cast<float4*>(dst)         = make_float4(a.x, a.z, b.x, b.z);
            *reinterpret_cast<float4*>(dst + CHUNK) = make_float4(a.y, a.w, b.y, b.w);
        }
    }
}

extern "C" void kernel_launch(void* const* d_in, const int* in_sizes, int n_in,
                              void* d_out, int out_size)
{
    const float* x  = (const float*)d_in[0];   // (B, C, L) float32
    const float* Bs = (const float*)d_in[1];   // (B, C, K, 3) float32
    const float* As = (const float*)d_in[2];   // (B, C, K, 3) float32
    float* y = (float*)d_out;                  // (B, C, L) float32

    const int dyn_bytes = SMEM_FLOATS * sizeof(float);   // 34816

    pass_a_kernel<<<NCHAN * NSUB, CTA_T, dyn_bytes>>>(x, Bs, As);
    scan_kernel<<<NCHAN, 1024>>>(Bs, As);
    pass_c_kernel<<<NCHAN * NSUB, CTA_T, dyn_bytes>>>(x, Bs, As, y);
}